// round 13
// baseline (speedup 1.0000x reference)
#include <cuda_runtime.h>
#include <math.h>
#include <stdint.h>

// Problem constants
#define BB 4
#define NN 8192
#define KK 16
#define BNK (BB * NN * KK)   // 524288

#define W_GRID_BLOCKS (16 * 32 * 4)  // w_pass grid size (x*y*z) = 2048
// ring 4 slots * 4 rows * 256thr * 8B = 32KB; shS 16KB; rn/rd 2KB
#define DYN_SMEM (4*4*256*8 + 256*16*4 + 2*256*4)   // 51200

// ---------------------------------------------------------------------------
// Device scratch (no allocations allowed)
// ---------------------------------------------------------------------------
__device__ float    g_S[BNK];            // softmax(logits)
__device__ double   g_StS[BB * KK * KK]; // per-batch S^T S (1024 doubles)
__device__ double   g_num;               // sum W[n,m] * dot(S_n, S_m)
__device__ double   g_den;               // sum W
__device__ unsigned g_done;              // finished-block counter

// ---------------------------------------------------------------------------
// Packed f32x2 helpers
// ---------------------------------------------------------------------------
typedef unsigned long long u64p; // carrier for packed 2 x fp32

__device__ __forceinline__ u64p pk2(float lo, float hi) {
    u64p d;
    asm("mov.b64 %0, {%1, %2};" : "=l"(d) : "f"(lo), "f"(hi));
    return d;
}
__device__ __forceinline__ u64p mul2(u64p a, u64p b) {
    u64p d;
    asm("mul.rn.f32x2 %0, %1, %2;" : "=l"(d) : "l"(a), "l"(b));
    return d;
}
__device__ __forceinline__ u64p fma2(u64p a, u64p b, u64p c) {
    u64p d;
    asm("fma.rn.f32x2 %0, %1, %2, %3;" : "=l"(d) : "l"(a), "l"(b), "l"(c));
    return d;
}
__device__ __forceinline__ float hsum2(u64p d) {
    float lo, hi;
    asm("mov.b64 {%0, %1}, %2;" : "=f"(lo), "=f"(hi) : "l"(d));
    return lo + hi;
}

// ---------------------------------------------------------------------------
// cp.async helper: 8B per thread (.ca — .cg supports only 16B)
// ---------------------------------------------------------------------------
__device__ __forceinline__ void cp_async8(uint32_t smem_addr, const void* gptr) {
    asm volatile("cp.async.ca.shared.global [%0], [%1], 8;"
                 :: "r"(smem_addr), "l"(gptr) : "memory");
}
#define CP_COMMIT() asm volatile("cp.async.commit_group;" ::: "memory")
#define CP_WAIT3()  asm volatile("cp.async.wait_group 3;" ::: "memory")

// ---------------------------------------------------------------------------
// Softmax over K=16 per row. One thread per row. Block 0 zeroes ALL
// accumulators (strided — 1024 StS entries > 256 threads).
// ---------------------------------------------------------------------------
__global__ void softmax_kernel(const float* __restrict__ logits,
                               float* __restrict__ outS) {
    if (blockIdx.x == 0) {
        int t = threadIdx.x;
        for (int i = t; i < BB * KK * KK; i += 256) g_StS[i] = 0.0;
        if (t == 0) { g_num = 0.0; g_den = 0.0; }
    }
    int row = blockIdx.x * blockDim.x + threadIdx.x; // 0 .. B*N-1
    const float4* lp = (const float4*)(logits + (size_t)row * KK);
    float4 v0 = lp[0], v1 = lp[1], v2 = lp[2], v3 = lp[3];
    float v[16] = { v0.x, v0.y, v0.z, v0.w, v1.x, v1.y, v1.z, v1.w,
                    v2.x, v2.y, v2.z, v2.w, v3.x, v3.y, v3.z, v3.w };
    float mx = v[0];
#pragma unroll
    for (int i = 1; i < 16; i++) mx = fmaxf(mx, v[i]);
    float s = 0.f;
#pragma unroll
    for (int i = 0; i < 16; i++) { v[i] = expf(v[i] - mx); s += v[i]; }
    float inv = 1.0f / s;
    float4 o0 = make_float4(v[0]*inv,  v[1]*inv,  v[2]*inv,  v[3]*inv);
    float4 o1 = make_float4(v[4]*inv,  v[5]*inv,  v[6]*inv,  v[7]*inv);
    float4 o2 = make_float4(v[8]*inv,  v[9]*inv,  v[10]*inv, v[11]*inv);
    float4 o3 = make_float4(v[12]*inv, v[13]*inv, v[14]*inv, v[15]*inv);
    float4* sp = (float4*)(g_S + (size_t)row * KK);
    sp[0] = o0; sp[1] = o1; sp[2] = o2; sp[3] = o3;
    if (outS) {
        float4* op = (float4*)(outS + (size_t)row * KK);
        op[0] = o0; op[1] = o1; op[2] = o2; op[3] = o3;
    }
}

// ---------------------------------------------------------------------------
// Fused main pass:
//   num += W[b,n,m] * dot16(S_n, S_m);  den += W[b,n,m]
//   + StS partials (blockIdx.x==0 blocks, from the resident shS tile)
//   + finalize (last block writes the loss)
//
// Block: 256 threads = 8 warps, 3 CTAs/SM (24 warps — the R12 fix: occupancy,
// not prefetch depth, was limiting DRAM%). Each thread owns 2 consecutive
// columns m (S_m packed in 32 regs). 256 S_n rows staged once in 16KB smem,
// read as ulonglong2 (packed pairs, zero MOVs). W streams through a 4-slot
// cp.async ring, 8B/thread/row, prefetch distance 3, per-thread wait_group
// (each thread copies exactly what it alone reads -> no barriers).
// Grid: (16 col strips, 32 row groups, B) = 2048 blocks.
// ---------------------------------------------------------------------------
__global__ void __launch_bounds__(256, 3)
w_pass_kernel(const float* __restrict__ W, float* __restrict__ out,
              int loss_idx) {
    extern __shared__ char dyn[];
    float2* shW = (float2*)dyn;                        // [4][4][256] 8B = 32KB
    float*  shS = (float*)(dyn + 4 * 4 * 256 * 8);     // 256 rows x 16 = 16KB
    float*  rn  = shS + 256 * 16;                      // 1KB
    float*  rd  = rn + 256;                            // 1KB

    const int tid  = threadIdx.x;
    const int lane = tid & 31;
    const int warp = tid >> 5;
    const int b  = blockIdx.z;
    const int c0 = (blockIdx.x * 8 + warp) * 64 + lane * 2; // 2 columns m
    const int r0 = blockIdx.y * 256;                         // 256 rows

    // byte address of this thread's 8B slot in shW plane 0
    const uint32_t swbase = (uint32_t)__cvta_generic_to_shared(&shW[tid]);
    const uint32_t plane  = 256 * 8;           // one row-in-chunk plane (2KB)
    const uint32_t slotsz = 4 * plane;         // one ring slot (4 rows, 8KB)

    // Stage 256 S_n rows (16KB) once
    {
        const float4* src = (const float4*)(g_S + ((size_t)b * NN + r0) * KK);
        float4* dst = (float4*)shS;
        dst[tid]       = src[tid];
        dst[tid + 256] = src[tid + 256];
        dst[tid + 512] = src[tid + 512];
        dst[tid + 768] = src[tid + 768];
    }

    // Pre-pack S_m for this thread's 2 columns: 2 x 8 packed pairs (32 regs)
    u64p sm[2][8];
#pragma unroll
    for (int jj = 0; jj < 2; jj++) {
        const float4* sp = (const float4*)(g_S + ((size_t)b * NN + (c0 + jj)) * KK);
        float4 a = __ldg(sp), b4 = __ldg(sp + 1), c = __ldg(sp + 2), d = __ldg(sp + 3);
        sm[jj][0] = pk2(a.x, a.y);   sm[jj][1] = pk2(a.z, a.w);
        sm[jj][2] = pk2(b4.x, b4.y); sm[jj][3] = pk2(b4.z, b4.w);
        sm[jj][4] = pk2(c.x, c.y);   sm[jj][5] = pk2(c.z, c.w);
        sm[jj][6] = pk2(d.x, d.y);   sm[jj][7] = pk2(d.z, d.w);
    }
    __syncthreads();   // shS tile resident

    const float* Wp = W + ((size_t)b * NN + r0) * NN + c0;

    // Prologue: chunks 0,1,2 into slots 0,1,2 (one commit group each)
#pragma unroll
    for (int k = 0; k < 3; k++) {
        const float* p = Wp + (size_t)k * 4 * NN;
        const uint32_t sb = swbase + (uint32_t)k * slotsz;
#pragma unroll
        for (int i = 0; i < 4; i++)
            cp_async8(sb + (uint32_t)i * plane, p + (size_t)i * NN);
        CP_COMMIT();
    }

    u64p acc0 = 0, acc1 = 0;      // packed num accumulators (one per column)
    float den0 = 0.f, den1 = 0.f; // den accumulators

#pragma unroll 1
    for (int k = 0; k < 64; k++) {               // 64 chunks x 4 rows
        const int slot = k & 3;
        // Issue chunk k+3 (empty commit on the tail keeps group count exact
        // so wait_group 3 always means "chunk k resident").
        if (k + 3 < 64) {
            const float* p = Wp + (size_t)(k + 3) * 4 * NN;
            const uint32_t sb = swbase + (uint32_t)((k + 3) & 3) * slotsz;
#pragma unroll
            for (int i = 0; i < 4; i++)
                cp_async8(sb + (uint32_t)i * plane, p + (size_t)i * NN);
        }
        CP_COMMIT();
        CP_WAIT3();   // chunk k resident

#pragma unroll
        for (int i = 0; i < 4; i++) {
            float2 w = shW[(size_t)slot * 1024 + (size_t)i * 256 + tid];
            // S_n row as packed pairs straight from smem (no MOVs)
            const ulonglong2* sp =
                (const ulonglong2*)(shS + (size_t)(k * 4 + i) * KK);
            ulonglong2 p0 = sp[0], p1 = sp[1];   // broadcast LDS.128
            u64p sn0 = p0.x, sn1 = p0.y, sn2 = p1.x, sn3 = p1.y;
            ulonglong2 p2 = sp[2], p3 = sp[3];
            u64p sn4 = p2.x, sn5 = p2.y, sn6 = p3.x, sn7 = p3.y;

            // 2 independent packed dot chains (dep gap 4cyc = fma latency)
            u64p d0 = mul2(sm[0][0], sn0);
            u64p d1 = mul2(sm[1][0], sn0);
            d0 = fma2(sm[0][1], sn1, d0); d1 = fma2(sm[1][1], sn1, d1);
            d0 = fma2(sm[0][2], sn2, d0); d1 = fma2(sm[1][2], sn2, d1);
            d0 = fma2(sm[0][3], sn3, d0); d1 = fma2(sm[1][3], sn3, d1);
            d0 = fma2(sm[0][4], sn4, d0); d1 = fma2(sm[1][4], sn4, d1);
            d0 = fma2(sm[0][5], sn5, d0); d1 = fma2(sm[1][5], sn5, d1);
            d0 = fma2(sm[0][6], sn6, d0); d1 = fma2(sm[1][6], sn6, d1);
            d0 = fma2(sm[0][7], sn7, d0); d1 = fma2(sm[1][7], sn7, d1);

            acc0 = fma2(pk2(w.x, w.x), d0, acc0);
            acc1 = fma2(pk2(w.y, w.y), d1, acc1);
            den0 += w.x;
            den1 += w.y;
        }
    }

    float tnum = hsum2(acc0) + hsum2(acc1);
    float tden = den0 + den1;

    // Block reduction -> one double atomic per block
    __syncthreads();
    rn[tid] = tnum; rd[tid] = tden;
    __syncthreads();
#pragma unroll
    for (int s = 128; s > 0; s >>= 1) {
        if (tid < s) { rn[tid] += rn[tid + s]; rd[tid] += rd[tid + s]; }
        __syncthreads();
    }
    if (tid == 0) {
        atomicAdd(&g_num, (double)rn[0]);
        atomicAdd(&g_den, (double)rd[0]);
    }

    // Fused StS partial: the x==0 blocks cover every row of every batch
    // exactly once; shS is still resident.
    if (blockIdx.x == 0) {
        int k = tid >> 4, j = tid & 15;
        float a0 = 0.f, a1 = 0.f;
#pragma unroll 4
        for (int r = 0; r < 256; r += 2) {
            a0 = fmaf(shS[r * 16 + k],       shS[r * 16 + j],       a0);
            a1 = fmaf(shS[(r + 1) * 16 + k], shS[(r + 1) * 16 + j], a1);
        }
        atomicAdd(&g_StS[b * 256 + tid], (double)(a0 + a1));
    }

    // Fused finalize: last block to finish computes the loss.
    __threadfence();
    __syncthreads();
    __shared__ unsigned s_isLast;
    if (tid == 0)
        s_isLast = (atomicAdd(&g_done, 1u) == W_GRID_BLOCKS - 1) ? 1u : 0u;
    __syncthreads();
    if (s_isLast) {
        int k = tid >> 4, j = tid & 15;
        float s = 0.f;
#pragma unroll
        for (int bi = 0; bi < BB; bi++) {
            float v = (float)__ldcg(&g_StS[bi * 256 + tid]); // L2 (bypass L1)
            float diff = v - (k == j ? 1.0f : 0.0f);
            s += diff * diff;
        }
        rn[tid] = s;
        __syncthreads();
#pragma unroll
        for (int st = 128; st > 0; st >>= 1) {
            if (tid < st) rn[tid] += rn[tid + st];
            __syncthreads();
        }
        if (tid == 0) {
            float ortho = sqrtf(rn[0]) / (float)BB;
            double num = __ldcg(&g_num), den = __ldcg(&g_den);
            out[loss_idx] = -(float)(num / den) + ortho;
            atomicExch(&g_done, 0u);  // reset for next replay
        }
    }
}

// ---------------------------------------------------------------------------
// Launch
// ---------------------------------------------------------------------------
extern "C" void kernel_launch(void* const* d_in, const int* in_sizes, int n_in,
                              void* d_out, int out_size) {
    const float* W = nullptr;
    const float* logits = nullptr;
    for (int i = 0; i < n_in; i++) {
        long sz = (long)in_sizes[i];
        if (sz == (long)BB * NN * NN)      W      = (const float*)d_in[i];
        else if (sz == (long)BB * NN * KK) logits = (const float*)d_in[i];
        // features [B,N,D] is unused by the reference computation
    }
    float* out = (float*)d_out;

    bool want_S    = (out_size >= BNK);
    bool want_loss = (out_size == 1) || (out_size == BNK + 1);

    cudaFuncSetAttribute(w_pass_kernel,
                         cudaFuncAttributeMaxDynamicSharedMemorySize, DYN_SMEM);

    softmax_kernel<<<(BB * NN) / 256, 256>>>(logits, want_S ? out : nullptr);
    if (want_loss) {
        int loss_idx = (out_size == 1) ? 0 : BNK;
        w_pass_kernel<<<dim3(NN / 512, NN / 256, BB), 256, DYN_SMEM>>>(
            W, out, loss_idx);
    }
}